// round 2
// baseline (speedup 1.0000x reference)
#include <cuda_runtime.h>
#include <cstdint>
#include <cstddef>

#define DMODEL 1024
#define NHEADS 16
#define DK 64
#define BATCH 2
#define SEQ 2048
#define MTOT (BATCH*SEQ)   // 4096

// Scratch (allocation-free rule: __device__ globals)
__device__ float g_q[MTOT*DMODEL];
__device__ float g_k[MTOT*DMODEL];
__device__ float g_v[MTOT*DMODEL];
__device__ float g_o[MTOT*DMODEL];

// ---------------- helpers ----------------
__device__ __forceinline__ uint32_t f2tf(float f){
    uint32_t u; asm("cvt.rna.tf32.f32 %0, %1;" : "=r"(u) : "f"(f)); return u;
}
__device__ __forceinline__ float f2tff(float f){ return __uint_as_float(f2tf(f)); }
__device__ __forceinline__ float ex2f(float x){
    float y; asm("ex2.approx.f32 %0, %1;" : "=f"(y) : "f"(x)); return y;
}
#define U(x) __float_as_uint(x)

__device__ __forceinline__ void mma_tf32(float&c0,float&c1,float&c2,float&c3,
    uint32_t a0,uint32_t a1,uint32_t a2,uint32_t a3,uint32_t b0,uint32_t b1){
    asm volatile("mma.sync.aligned.m16n8k8.row.col.f32.tf32.tf32.f32 "
        "{%0,%1,%2,%3},{%4,%5,%6,%7},{%8,%9},{%0,%1,%2,%3};\n"
        : "+f"(c0),"+f"(c1),"+f"(c2),"+f"(c3)
        : "r"(a0),"r"(a1),"r"(a2),"r"(a3),"r"(b0),"r"(b1));
}

// column permutation within each 8-group: k -> (k&~7) + 2*(k&3) + ((k>>2)&1)
// makes the mma pair (k0+c, k0+c+4) adjacent -> one LDS.64
__device__ __forceinline__ int kperm(int k){ return (k & ~7) + 2*(k&3) + ((k>>2)&1); }

// ---------------- GEMM: C[M,N] = A[M,K] @ W[K,N] + bias ----------------
// BM=128 BN=128 BK=32, 256 threads, warp grid 2(M)x4(N), warp tile 64x32.
// smem holds tf32-converted data; A is column-permuted for LDS.64 a-frags.
#define GBM 128
#define GBN 128
#define GBK 32
#define AST 68
#define BST 136
#define A_SZ (GBM*AST)
#define B_SZ (GBK*BST)
#define GSMEM ((2*A_SZ + 2*B_SZ)*4)

__global__ __launch_bounds__(256) void gemm_tf32(
        const float* __restrict__ A, const float* __restrict__ W,
        const float* __restrict__ bias, float* __restrict__ C,
        int M, int N, int K){
    extern __shared__ float sm[];
    float* As = sm;            // [2][128][AST] perm'd tf32
    float* Bs = sm + 2*A_SZ;   // [2][32][BST]  straight tf32
    const int tid = threadIdx.x;
    const int warp = tid>>5, lane = tid&31;
    const int wm = warp>>2, wn = warp&3;
    const int bm = blockIdx.y*GBM, bn = blockIdx.x*GBN;

    const int ar = tid>>3, ac = (tid&7)*4;    // A tile 128x32
    const int br = tid>>5, bc = (tid&31)*4;   // B tile 32x128

    const float* Abase = A + (size_t)bm*K;
    const float* Wbase = W + bn;

    float acc[4][4][4] = {};
    float4 areg[4], breg[4];

    auto ldg = [&](int kt){
        #pragma unroll
        for(int i=0;i<4;i++){
            areg[i] = *(const float4*)&Abase[(size_t)(ar+32*i)*K + kt*GBK + ac];
            breg[i] = *(const float4*)&Wbase[(size_t)(kt*GBK + br + 8*i)*N + bc];
        }
    };
    auto sts = [&](int st){
        float* as = As + st*A_SZ;
        float* bs = Bs + st*B_SZ;
        #pragma unroll
        for(int i=0;i<4;i++){
            const int rb = (ar+32*i)*AST + (ac & ~7) + ((ac>>2)&1);
            as[rb]   = f2tff(areg[i].x);
            as[rb+2] = f2tff(areg[i].y);
            as[rb+4] = f2tff(areg[i].z);
            as[rb+6] = f2tff(areg[i].w);
            float4 t = make_float4(f2tff(breg[i].x), f2tff(breg[i].y),
                                   f2tff(breg[i].z), f2tff(breg[i].w));
            *(float4*)&bs[(br+8*i)*BST + bc] = t;
        }
    };

    const int NT = K/GBK;
    ldg(0); sts(0); ldg(1);
    __syncthreads();

    #pragma unroll 1
    for(int kt=0; kt<NT; kt++){
        const int st = kt&1;
        if(kt+1<NT) sts(st^1);
        if(kt+2<NT) ldg(kt+2);
        const float* as = As + st*A_SZ;
        const float* bs = Bs + st*B_SZ;
        #pragma unroll
        for(int ks=0; ks<4; ks++){
            const int k0 = ks*8;
            float2 alo[4], ahi[4];
            #pragma unroll
            for(int mt=0;mt<4;mt++){
                const int r = wm*64 + mt*16 + (lane>>2);
                alo[mt] = *(const float2*)&as[r*AST     + k0 + 2*(lane&3)];
                ahi[mt] = *(const float2*)&as[(r+8)*AST + k0 + 2*(lane&3)];
            }
            uint32_t bf[4][2];
            #pragma unroll
            for(int nt=0;nt<4;nt++){
                const int n = wn*32 + nt*8 + (lane>>2);
                bf[nt][0] = U(bs[(k0+(lane&3))*BST + n]);
                bf[nt][1] = U(bs[(k0+(lane&3)+4)*BST + n]);
            }
            #pragma unroll
            for(int mt=0;mt<4;mt++)
                #pragma unroll
                for(int nt=0;nt<4;nt++)
                    mma_tf32(acc[mt][nt][0],acc[mt][nt][1],acc[mt][nt][2],acc[mt][nt][3],
                             U(alo[mt].x),U(ahi[mt].x),U(alo[mt].y),U(ahi[mt].y),
                             bf[nt][0],bf[nt][1]);
        }
        __syncthreads();
    }
    // epilogue with bias
    #pragma unroll
    for(int mt=0;mt<4;mt++){
        const int r0 = bm + wm*64 + mt*16 + (lane>>2);
        #pragma unroll
        for(int nt=0;nt<4;nt++){
            const int c0 = bn + wn*32 + nt*8 + 2*(lane&3);
            const float b0 = bias[c0], b1 = bias[c0+1];
            *(float2*)&C[(size_t)r0*N + c0]     = make_float2(acc[mt][nt][0]+b0, acc[mt][nt][1]+b1);
            *(float2*)&C[(size_t)(r0+8)*N + c0] = make_float2(acc[mt][nt][2]+b0, acc[mt][nt][3]+b1);
        }
    }
}

// ---------------- Flash attention ----------------
// Br=128, Bc=64, Dk=64. 8 warps x 16 query rows. smem holds tf32-converted
// data; Q and K column-permuted for LDS.64 fragments. One sync per j-iter:
// STS next tile into idle buffer, LDG two tiles ahead into registers.
#define ABR 128
#define ABC 64
#define QS 68
#define PS 68
#define KS 76
#define VS 72
#define ASMEM ((ABR*QS + ABR*PS + 2*ABC*KS + 2*ABC*VS)*4)

__global__ __launch_bounds__(256) void attn_tf32(
        const float* __restrict__ Q, const float* __restrict__ K,
        const float* __restrict__ V, float* __restrict__ O){
    extern __shared__ float sm[];
    float* Qp = sm;                       // [128][QS] perm'd tf32
    float* Ps = Qp + ABR*QS;              // [128][PS] tf32
    float* Ks = Ps + ABR*PS;              // [2][64][KS] perm'd tf32
    float* Vs = Ks + 2*ABC*KS;            // [2][64][VS] straight tf32

    const int tid = threadIdx.x, warp = tid>>5, lane = tid&31;
    const int qt = blockIdx.x, h = blockIdx.y, b = blockIdx.z;

    const float* Qg = Q + ((size_t)(b*SEQ + qt*ABR))*DMODEL + h*DK;
    const float* Kg = K + ((size_t)(b*SEQ))*DMODEL + h*DK;
    const float* Vg = V + ((size_t)(b*SEQ))*DMODEL + h*DK;

    const int lr = tid>>4, lc = (tid&15)*4;

    float4 kreg[4], vreg[4];
    auto ldgKV = [&](int j){
        const float* kp = Kg + (size_t)(j*ABC)*DMODEL;
        const float* vp = Vg + (size_t)(j*ABC)*DMODEL;
        #pragma unroll
        for(int i=0;i<4;i++){
            kreg[i] = *(const float4*)&kp[(size_t)(lr+16*i)*DMODEL + lc];
            vreg[i] = *(const float4*)&vp[(size_t)(lr+16*i)*DMODEL + lc];
        }
    };
    auto stsKV = [&](int st){
        float* ks = Ks + st*ABC*KS;
        float* vs = Vs + st*ABC*VS;
        #pragma unroll
        for(int i=0;i<4;i++){
            const int rb = (lr+16*i)*KS + (lc & ~7) + ((lc>>2)&1);
            ks[rb]   = f2tff(kreg[i].x);
            ks[rb+2] = f2tff(kreg[i].y);
            ks[rb+4] = f2tff(kreg[i].z);
            ks[rb+6] = f2tff(kreg[i].w);
            float4 t = make_float4(f2tff(vreg[i].x), f2tff(vreg[i].y),
                                   f2tff(vreg[i].z), f2tff(vreg[i].w));
            *(float4*)&vs[(lr+16*i)*VS + lc] = t;
        }
    };

    // one-time Q load + cvt + perm'd STS
    #pragma unroll
    for(int i=0;i<8;i++){
        float4 q4 = *(const float4*)&Qg[(size_t)(lr+16*i)*DMODEL + lc];
        const int rb = (lr+16*i)*QS + (lc & ~7) + ((lc>>2)&1);
        Qp[rb]   = f2tff(q4.x);
        Qp[rb+2] = f2tff(q4.y);
        Qp[rb+4] = f2tff(q4.z);
        Qp[rb+6] = f2tff(q4.w);
    }

    ldgKV(0); stsKV(0); ldgKV(1);
    __syncthreads();

    float o[8][4] = {};
    float m0=-1e30f, m1=-1e30f, l0=0.f, l1=0.f;
    const float SCALE = 0.125f * 1.4426950408889634f;   // 1/sqrt(64) * log2(e)
    const int rloc = warp*16 + (lane>>2);

    const int NJ = SEQ/ABC;   // 32
    #pragma unroll 1
    for(int j=0;j<NJ;j++){
        const int st = j&1;
        if(j+1<NJ) stsKV(st^1);
        if(j+2<NJ) ldgKV(j+2);
        const float* ks = Ks + st*ABC*KS;
        const float* vs = Vs + st*ABC*VS;

        // S = Q @ K^T  (per-warp 16x64)
        float s[8][4] = {};
        #pragma unroll
        for(int kr=0;kr<8;kr++){
            const int k0 = kr*8;
            const float2 alo = *(const float2*)&Qp[rloc*QS     + k0 + 2*(lane&3)];
            const float2 ahi = *(const float2*)&Qp[(rloc+8)*QS + k0 + 2*(lane&3)];
            #pragma unroll
            for(int nt=0;nt<8;nt++){
                const int n = nt*8 + (lane>>2);
                const float2 bb = *(const float2*)&ks[n*KS + k0 + 2*(lane&3)];
                mma_tf32(s[nt][0],s[nt][1],s[nt][2],s[nt][3],
                         U(alo.x),U(ahi.x),U(alo.y),U(ahi.y),U(bb.x),U(bb.y));
            }
        }

        // online softmax in base-2 scaled domain
        float tm0=-1e30f, tm1=-1e30f;
        #pragma unroll
        for(int nt=0;nt<8;nt++){
            s[nt][0]*=SCALE; s[nt][1]*=SCALE; s[nt][2]*=SCALE; s[nt][3]*=SCALE;
            tm0=fmaxf(tm0,fmaxf(s[nt][0],s[nt][1]));
            tm1=fmaxf(tm1,fmaxf(s[nt][2],s[nt][3]));
        }
        tm0=fmaxf(tm0,__shfl_xor_sync(0xffffffffu,tm0,1));
        tm0=fmaxf(tm0,__shfl_xor_sync(0xffffffffu,tm0,2));
        tm1=fmaxf(tm1,__shfl_xor_sync(0xffffffffu,tm1,1));
        tm1=fmaxf(tm1,__shfl_xor_sync(0xffffffffu,tm1,2));
        const float nm0=fmaxf(m0,tm0), nm1=fmaxf(m1,tm1);
        const float al0=ex2f(m0-nm0), al1=ex2f(m1-nm1);
        float ts0=0.f, ts1=0.f;
        #pragma unroll
        for(int nt=0;nt<8;nt++){
            s[nt][0]=ex2f(s[nt][0]-nm0); s[nt][1]=ex2f(s[nt][1]-nm0);
            s[nt][2]=ex2f(s[nt][2]-nm1); s[nt][3]=ex2f(s[nt][3]-nm1);
            ts0 += s[nt][0]+s[nt][1];
            ts1 += s[nt][2]+s[nt][3];
        }
        ts0 += __shfl_xor_sync(0xffffffffu,ts0,1);
        ts0 += __shfl_xor_sync(0xffffffffu,ts0,2);
        ts1 += __shfl_xor_sync(0xffffffffu,ts1,1);
        ts1 += __shfl_xor_sync(0xffffffffu,ts1,2);
        l0 = l0*al0 + ts0;  l1 = l1*al1 + ts1;
        m0 = nm0; m1 = nm1;
        #pragma unroll
        for(int nt=0;nt<8;nt++){
            o[nt][0]*=al0; o[nt][1]*=al0; o[nt][2]*=al1; o[nt][3]*=al1;
        }
        // P -> smem, pre-converted to tf32 (warp-private rows)
        #pragma unroll
        for(int nt=0;nt<8;nt++){
            const int c = nt*8 + 2*(lane&3);
            *(float2*)&Ps[rloc*PS + c]     = make_float2(f2tff(s[nt][0]), f2tff(s[nt][1]));
            *(float2*)&Ps[(rloc+8)*PS + c] = make_float2(f2tff(s[nt][2]), f2tff(s[nt][3]));
        }
        __syncwarp();

        // O += P @ V
        #pragma unroll
        for(int kr=0;kr<8;kr++){
            const int k0 = kr*8;
            const uint32_t a0=U(Ps[rloc*PS     + k0 + (lane&3)]);
            const uint32_t a1=U(Ps[(rloc+8)*PS + k0 + (lane&3)]);
            const uint32_t a2=U(Ps[rloc*PS     + k0 + (lane&3)+4]);
            const uint32_t a3=U(Ps[(rloc+8)*PS + k0 + (lane&3)+4]);
            #pragma unroll
            for(int nt=0;nt<8;nt++){
                const int n = nt*8 + (lane>>2);
                const uint32_t b0=U(vs[(k0+(lane&3))*VS + n]);
                const uint32_t b1=U(vs[(k0+(lane&3)+4)*VS + n]);
                mma_tf32(o[nt][0],o[nt][1],o[nt][2],o[nt][3],a0,a1,a2,a3,b0,b1);
            }
        }
        __syncthreads();
    }

    // epilogue
    const float inv0 = 1.f/l0, inv1 = 1.f/l1;
    const int r = b*SEQ + qt*ABR + warp*16 + (lane>>2);
    #pragma unroll
    for(int nt=0;nt<8;nt++){
        const int c = h*DK + nt*8 + 2*(lane&3);
        *(float2*)&O[(size_t)r*DMODEL + c] =
            make_float2(o[nt][0]*inv0, o[nt][1]*inv0);
        *(float2*)&O[(size_t)(r+8)*DMODEL + c] =
            make_float2(o[nt][2]*inv1, o[nt][3]*inv1);
    }
}

// ---------------- launch ----------------
extern "C" void kernel_launch(void* const* d_in, const int* in_sizes, int n_in,
                              void* d_out, int out_size){
    const float* x  = (const float*)d_in[0];
    const float* Wq = (const float*)d_in[1];
    const float* bq = (const float*)d_in[2];
    const float* Wk = (const float*)d_in[3];
    const float* bk = (const float*)d_in[4];
    const float* Wv = (const float*)d_in[5];
    const float* bv = (const float*)d_in[6];
    const float* Wo = (const float*)d_in[7];
    const float* bo = (const float*)d_in[8];
    float* out = (float*)d_out;

    float *q, *k, *v, *o;
    cudaGetSymbolAddress((void**)&q, g_q);
    cudaGetSymbolAddress((void**)&k, g_k);
    cudaGetSymbolAddress((void**)&v, g_v);
    cudaGetSymbolAddress((void**)&o, g_o);

    cudaFuncSetAttribute(gemm_tf32, cudaFuncAttributeMaxDynamicSharedMemorySize, GSMEM);
    cudaFuncSetAttribute(attn_tf32, cudaFuncAttributeMaxDynamicSharedMemorySize, ASMEM);

    dim3 ggrid(DMODEL/GBN, MTOT/GBM);   // (8, 32)
    gemm_tf32<<<ggrid, 256, GSMEM>>>(x, Wq, bq, q, MTOT, DMODEL, DMODEL);
    gemm_tf32<<<ggrid, 256, GSMEM>>>(x, Wk, bk, k, MTOT, DMODEL, DMODEL);
    gemm_tf32<<<ggrid, 256, GSMEM>>>(x, Wv, bv, v, MTOT, DMODEL, DMODEL);

    dim3 agrid(SEQ/ABR, NHEADS, BATCH); // (16, 16, 2)
    attn_tf32<<<agrid, 256, ASMEM>>>(q, k, v, o);

    gemm_tf32<<<ggrid, 256, GSMEM>>>(o, Wo, bo, out, MTOT, DMODEL, DMODEL);
}

// round 4
// speedup vs baseline: 1.2902x; 1.2902x over previous
#include <cuda_runtime.h>
#include <cstdint>
#include <cstddef>

#define DMODEL 1024
#define NHEADS 16
#define DK 64
#define BATCH 2
#define SEQ 2048
#define MTOT (BATCH*SEQ)   // 4096

// Scratch (allocation-free rule: __device__ globals)
__device__ float g_q[MTOT*DMODEL];
__device__ float g_k[MTOT*DMODEL];
__device__ float g_v[MTOT*DMODEL];
__device__ float g_o[MTOT*DMODEL];

// ---------------- PTX helpers ----------------
__device__ __forceinline__ uint32_t f2tf(float f){
    uint32_t u; asm("cvt.rna.tf32.f32 %0, %1;" : "=r"(u) : "f"(f)); return u;
}
__device__ __forceinline__ float ex2f(float x){
    float y; asm("ex2.approx.f32 %0, %1;" : "=f"(y) : "f"(x)); return y;
}
__device__ __forceinline__ void mma_tf32(float&c0,float&c1,float&c2,float&c3,
    uint32_t a0,uint32_t a1,uint32_t a2,uint32_t a3,uint32_t b0,uint32_t b1){
    asm volatile("mma.sync.aligned.m16n8k8.row.col.f32.tf32.tf32.f32 "
        "{%0,%1,%2,%3},{%4,%5,%6,%7},{%8,%9},{%0,%1,%2,%3};\n"
        : "+f"(c0),"+f"(c1),"+f"(c2),"+f"(c3)
        : "r"(a0),"r"(a1),"r"(a2),"r"(a3),"r"(b0),"r"(b1));
}
__device__ __forceinline__ void cp16(void* smem, const void* gmem){
    uint32_t s = (uint32_t)__cvta_generic_to_shared(smem);
    asm volatile("cp.async.cg.shared.global [%0], [%1], 16;\n" :: "r"(s), "l"(gmem));
}
__device__ __forceinline__ void cp_commit(){ asm volatile("cp.async.commit_group;\n"); }
template<int N> __device__ __forceinline__ void cp_wait(){
    asm volatile("cp.async.wait_group %0;\n" :: "n"(N));
}

// ---------------- GEMM: C[M,N] = A[M,K] @ W[K,N] + bias ----------------
// (identical to round-1 version: the fastest GEMM measured so far)
#define GBM 128
#define GBN 128
#define GBK 32
#define A_STRIDE 36     // (4r+c)%32 conflict-free frag reads
#define B_STRIDE 136    // (8k+n)%32 conflict-free frag reads
#define A_SZ (GBM*A_STRIDE)
#define B_SZ (GBK*B_STRIDE)
#define GSMEM ((2*A_SZ + 2*B_SZ)*4)

__global__ void gemm_tf32(const float* __restrict__ A, const float* __restrict__ W,
                          const float* __restrict__ bias, float* __restrict__ C,
                          int M, int N, int K){
    extern __shared__ float sm[];
    float* As = sm;            // [2][A_SZ]
    float* Bs = sm + 2*A_SZ;   // [2][B_SZ]
    const int tid = threadIdx.x;
    const int warp = tid>>5, lane = tid&31;
    const int wm = warp>>2;    // 0..1
    const int wn = warp&3;     // 0..3
    const int bm = blockIdx.y*GBM, bn = blockIdx.x*GBN;

    const int ar = tid>>3, ac = (tid&7)*4;    // A tile 128x32 loads
    const int br = tid>>5, bc = (tid&31)*4;   // B tile 32x128 loads

    float acc[4][4][4];
    #pragma unroll
    for(int i=0;i<4;i++)
        #pragma unroll
        for(int j=0;j<4;j++)
            #pragma unroll
            for(int r=0;r<4;r++) acc[i][j][r]=0.f;

    const int NT = K/GBK;
    auto prefetch = [&](int kt, int st){
        const float* Ap = A + (size_t)bm*K + kt*GBK;
        float* as = As + st*A_SZ;
        #pragma unroll
        for(int i=0;i<4;i++)
            cp16(&as[(ar+32*i)*A_STRIDE + ac], &Ap[(size_t)(ar+32*i)*K + ac]);
        const float* Wp = W + (size_t)(kt*GBK)*N + bn;
        float* bs = Bs + st*B_SZ;
        #pragma unroll
        for(int i=0;i<4;i++)
            cp16(&bs[(br+8*i)*B_STRIDE + bc], &Wp[(size_t)(br+8*i)*N + bc]);
    };
    prefetch(0,0); cp_commit();

    for(int kt=0; kt<NT; kt++){
        const int st = kt&1;
        if(kt+1<NT){ prefetch(kt+1, st^1); cp_commit(); cp_wait<1>(); }
        else       { cp_wait<0>(); }
        __syncthreads();
        float* as = As + st*A_SZ;
        float* bs = Bs + st*B_SZ;
        #pragma unroll
        for(int ks=0; ks<4; ks++){
            const int k0 = ks*8;
            uint32_t af[4][4]; uint32_t bf[4][2];
            #pragma unroll
            for(int mt=0; mt<4; mt++){
                const int r = wm*64 + mt*16 + (lane>>2);
                const int c = k0 + (lane&3);
                af[mt][0] = f2tf(as[r*A_STRIDE + c]);
                af[mt][1] = f2tf(as[(r+8)*A_STRIDE + c]);
                af[mt][2] = f2tf(as[r*A_STRIDE + c+4]);
                af[mt][3] = f2tf(as[(r+8)*A_STRIDE + c+4]);
            }
            #pragma unroll
            for(int nt=0; nt<4; nt++){
                const int n = wn*32 + nt*8 + (lane>>2);
                const int k = k0 + (lane&3);
                bf[nt][0] = f2tf(bs[k*B_STRIDE + n]);
                bf[nt][1] = f2tf(bs[(k+4)*B_STRIDE + n]);
            }
            #pragma unroll
            for(int mt=0;mt<4;mt++)
                #pragma unroll
                for(int nt=0;nt<4;nt++)
                    mma_tf32(acc[mt][nt][0],acc[mt][nt][1],acc[mt][nt][2],acc[mt][nt][3],
                             af[mt][0],af[mt][1],af[mt][2],af[mt][3],bf[nt][0],bf[nt][1]);
        }
        __syncthreads();
    }
    // epilogue with bias
    #pragma unroll
    for(int mt=0;mt<4;mt++){
        const int r0 = bm + wm*64 + mt*16 + (lane>>2);
        #pragma unroll
        for(int nt=0;nt<4;nt++){
            const int c0 = bn + wn*32 + nt*8 + 2*(lane&3);
            const float b0 = bias[c0], b1 = bias[c0+1];
            float2 v0 = make_float2(acc[mt][nt][0]+b0, acc[mt][nt][1]+b1);
            float2 v1 = make_float2(acc[mt][nt][2]+b0, acc[mt][nt][3]+b1);
            *(float2*)&C[(size_t)r0*N + c0]     = v0;
            *(float2*)&C[(size_t)(r0+8)*N + c0] = v1;
        }
    }
}

// ---------------- Flash attention (tf32 mma, online softmax) ----------------
// Br=128, Bc=32, Dk=64. 8 warps x 16 query rows. Shrunk working set (87KB)
// so 2 CTAs fit per SM -> 16 warps to hide LDS/bar latency.
#define ABR 128
#define ABC 32
#define QSTR 68
#define KSTR 68
#define VSTR 72
#define PSTR 36
#define ASMEM ((ABR*QSTR + ABR*PSTR + 2*ABC*KSTR + 2*ABC*VSTR)*4)

__global__ __launch_bounds__(256,2) void attn_tf32(
        const float* __restrict__ Q, const float* __restrict__ K,
        const float* __restrict__ V, float* __restrict__ O){
    extern __shared__ float sm[];
    float* Qs = sm;                       // [128][68]
    float* Ps = Qs + ABR*QSTR;            // [128][36]
    float* Ks = Ps + ABR*PSTR;            // [2][32][68]
    float* Vs = Ks + 2*ABC*KSTR;          // [2][32][72]

    const int tid = threadIdx.x, warp = tid>>5, lane = tid&31;
    const int qt = blockIdx.x;            // 0..15
    const int h  = blockIdx.y;            // 0..15
    const int b  = blockIdx.z;            // 0..1

    const float* Qg = Q + ((size_t)(b*SEQ + qt*ABR))*DMODEL + h*DK;
    const float* Kg = K + ((size_t)(b*SEQ))*DMODEL + h*DK;
    const float* Vg = V + ((size_t)(b*SEQ))*DMODEL + h*DK;

    const int lr = tid>>4, lc = (tid&15)*4;

    // load Q tile 128x64
    #pragma unroll
    for(int i=0;i<8;i++)
        cp16(&Qs[(lr+16*i)*QSTR + lc], &Qg[(size_t)(lr+16*i)*DMODEL + lc]);

    auto prefKV = [&](int j, int st){
        const float* kp = Kg + (size_t)(j*ABC)*DMODEL;
        const float* vp = Vg + (size_t)(j*ABC)*DMODEL;
        float* ks = Ks + st*ABC*KSTR;
        float* vs = Vs + st*ABC*VSTR;
        #pragma unroll
        for(int i=0;i<2;i++){
            cp16(&ks[(lr+16*i)*KSTR + lc], &kp[(size_t)(lr+16*i)*DMODEL + lc]);
            cp16(&vs[(lr+16*i)*VSTR + lc], &vp[(size_t)(lr+16*i)*DMODEL + lc]);
        }
    };
    prefKV(0,0); cp_commit();

    float o[8][4];
    #pragma unroll
    for(int nt=0;nt<8;nt++){ o[nt][0]=0.f;o[nt][1]=0.f;o[nt][2]=0.f;o[nt][3]=0.f; }
    float m0=-1e30f, m1=-1e30f, l0=0.f, l1=0.f;
    const float SCALE = 0.125f * 1.4426950408889634f;   // 1/sqrt(64) * log2(e)
    const int rloc = warp*16 + (lane>>2);

    const int NJ = SEQ/ABC;   // 64
    #pragma unroll 1
    for(int j=0;j<NJ;j++){
        const int st = j&1;
        if(j+1<NJ){ prefKV(j+1, st^1); cp_commit(); cp_wait<1>(); }
        else      { cp_wait<0>(); }
        __syncthreads();

        float* ks = Ks + st*ABC*KSTR;
        float* vs = Vs + st*ABC*VSTR;

        // S = Q @ K^T  (per-warp 16x32, contract over Dk=64)
        float s[4][4];
        #pragma unroll
        for(int nt=0;nt<4;nt++){ s[nt][0]=0.f;s[nt][1]=0.f;s[nt][2]=0.f;s[nt][3]=0.f; }
        #pragma unroll
        for(int ksr=0;ksr<8;ksr++){
            const int k0 = ksr*8;
            const uint32_t a0=f2tf(Qs[rloc*QSTR + k0 + (lane&3)]);
            const uint32_t a1=f2tf(Qs[(rloc+8)*QSTR + k0 + (lane&3)]);
            const uint32_t a2=f2tf(Qs[rloc*QSTR + k0 + (lane&3)+4]);
            const uint32_t a3=f2tf(Qs[(rloc+8)*QSTR + k0 + (lane&3)+4]);
            #pragma unroll
            for(int nt=0;nt<4;nt++){
                const int n = nt*8 + (lane>>2);
                const uint32_t b0=f2tf(ks[n*KSTR + k0 + (lane&3)]);
                const uint32_t b1=f2tf(ks[n*KSTR + k0 + (lane&3)+4]);
                mma_tf32(s[nt][0],s[nt][1],s[nt][2],s[nt][3],a0,a1,a2,a3,b0,b1);
            }
        }

        // online softmax (rows rloc, rloc+8) in base-2 scaled domain
        float tm0=-1e30f, tm1=-1e30f;
        #pragma unroll
        for(int nt=0;nt<4;nt++){
            s[nt][0]*=SCALE; s[nt][1]*=SCALE; s[nt][2]*=SCALE; s[nt][3]*=SCALE;
            tm0=fmaxf(tm0,fmaxf(s[nt][0],s[nt][1]));
            tm1=fmaxf(tm1,fmaxf(s[nt][2],s[nt][3]));
        }
        tm0=fmaxf(tm0,__shfl_xor_sync(0xffffffffu,tm0,1));
        tm0=fmaxf(tm0,__shfl_xor_sync(0xffffffffu,tm0,2));
        tm1=fmaxf(tm1,__shfl_xor_sync(0xffffffffu,tm1,1));
        tm1=fmaxf(tm1,__shfl_xor_sync(0xffffffffu,tm1,2));
        const float nm0=fmaxf(m0,tm0), nm1=fmaxf(m1,tm1);
        const float al0=ex2f(m0-nm0), al1=ex2f(m1-nm1);
        float ts0=0.f, ts1=0.f;
        #pragma unroll
        for(int nt=0;nt<4;nt++){
            s[nt][0]=ex2f(s[nt][0]-nm0); s[nt][1]=ex2f(s[nt][1]-nm0);
            s[nt][2]=ex2f(s[nt][2]-nm1); s[nt][3]=ex2f(s[nt][3]-nm1);
            ts0 += s[nt][0]+s[nt][1];
            ts1 += s[nt][2]+s[nt][3];
        }
        ts0 += __shfl_xor_sync(0xffffffffu,ts0,1);
        ts0 += __shfl_xor_sync(0xffffffffu,ts0,2);
        ts1 += __shfl_xor_sync(0xffffffffu,ts1,1);
        ts1 += __shfl_xor_sync(0xffffffffu,ts1,2);
        l0 = l0*al0 + ts0;  l1 = l1*al1 + ts1;
        m0 = nm0; m1 = nm1;
        #pragma unroll
        for(int nt=0;nt<8;nt++){
            o[nt][0]*=al0; o[nt][1]*=al0; o[nt][2]*=al1; o[nt][3]*=al1;
        }
        // P -> smem (warp-private rows; warp-level sync suffices)
        #pragma unroll
        for(int nt=0;nt<4;nt++){
            const int c = nt*8 + 2*(lane&3);
            *(float2*)&Ps[rloc*PSTR + c]     = make_float2(s[nt][0], s[nt][1]);
            *(float2*)&Ps[(rloc+8)*PSTR + c] = make_float2(s[nt][2], s[nt][3]);
        }
        __syncwarp();

        // O += P @ V  (contract over Bc=32)
        #pragma unroll
        for(int ksr=0;ksr<4;ksr++){
            const int k0 = ksr*8;
            const uint32_t a0=f2tf(Ps[rloc*PSTR + k0 + (lane&3)]);
            const uint32_t a1=f2tf(Ps[(rloc+8)*PSTR + k0 + (lane&3)]);
            const uint32_t a2=f2tf(Ps[rloc*PSTR + k0 + (lane&3)+4]);
            const uint32_t a3=f2tf(Ps[(rloc+8)*PSTR + k0 + (lane&3)+4]);
            #pragma unroll
            for(int nt=0;nt<8;nt++){
                const int n = nt*8 + (lane>>2);
                const uint32_t b0=f2tf(vs[(k0+(lane&3))*VSTR + n]);
                const uint32_t b1=f2tf(vs[(k0+(lane&3)+4)*VSTR + n]);
                mma_tf32(o[nt][0],o[nt][1],o[nt][2],o[nt][3],a0,a1,a2,a3,b0,b1);
            }
        }
        __syncthreads();  // protect Ks/Vs (next prefetch) and Ps
    }

    // epilogue
    const float inv0 = 1.f/l0, inv1 = 1.f/l1;
    const int r = b*SEQ + qt*ABR + warp*16 + (lane>>2);
    #pragma unroll
    for(int nt=0;nt<8;nt++){
        const int c = h*DK + nt*8 + 2*(lane&3);
        *(float2*)&O[(size_t)r*DMODEL + c] =
            make_float2(o[nt][0]*inv0, o[nt][1]*inv0);
        *(float2*)&O[(size_t)(r+8)*DMODEL + c] =
            make_float2(o[nt][2]*inv1, o[nt][3]*inv1);
    }
}

// ---------------- launch ----------------
extern "C" void kernel_launch(void* const* d_in, const int* in_sizes, int n_in,
                              void* d_out, int out_size){
    const float* x  = (const float*)d_in[0];
    const float* Wq = (const float*)d_in[1];
    const float* bq = (const float*)d_in[2];
    const float* Wk = (const float*)d_in[3];
    const float* bk = (const float*)d_in[4];
    const float* Wv = (const float*)d_in[5];
    const float* bv = (const float*)d_in[6];
    const float* Wo = (const float*)d_in[7];
    const float* bo = (const float*)d_in[8];
    float* out = (float*)d_out;

    float *q, *k, *v, *o;
    cudaGetSymbolAddress((void**)&q, g_q);
    cudaGetSymbolAddress((void**)&k, g_k);
    cudaGetSymbolAddress((void**)&v, g_v);
    cudaGetSymbolAddress((void**)&o, g_o);

    cudaFuncSetAttribute(gemm_tf32, cudaFuncAttributeMaxDynamicSharedMemorySize, GSMEM);
    cudaFuncSetAttribute(attn_tf32, cudaFuncAttributeMaxDynamicSharedMemorySize, ASMEM);

    dim3 ggrid(DMODEL/GBN, MTOT/GBM);   // (8, 32)
    gemm_tf32<<<ggrid, 256, GSMEM>>>(x, Wq, bq, q, MTOT, DMODEL, DMODEL);
    gemm_tf32<<<ggrid, 256, GSMEM>>>(x, Wk, bk, k, MTOT, DMODEL, DMODEL);
    gemm_tf32<<<ggrid, 256, GSMEM>>>(x, Wv, bv, v, MTOT, DMODEL, DMODEL);

    dim3 agrid(SEQ/ABR, NHEADS, BATCH); // (16, 16, 2)
    attn_tf32<<<agrid, 256, ASMEM>>>(q, k, v, o);

    gemm_tf32<<<ggrid, 256, GSMEM>>>(o, Wo, bo, out, MTOT, DMODEL, DMODEL);
}